// round 3
// baseline (speedup 1.0000x reference)
#include <cuda_runtime.h>
#include <cstdint>
#include <cstddef>

#define NB   32
#define CIN  128
#define HWD  56
#define OC   256
#define KTOT 1152           // 9 * 128, k = (r*3+s)*128 + c
#define NSTAGES 18          // 1152 / 64
#define SSTR 80             // padded smem row stride (conflict-free for both LDS pattern and 16B cp.async)

// Scratch (device globals; no runtime allocation allowed)
__device__ __align__(16) signed char g_x8[(size_t)NB * HWD * HWD * CIN]; // NHWC int8
__device__ __align__(16) signed char g_w8[(size_t)OC * KTOT];            // [oc][(r*3+s)*128 + c]

// ---------------------------------------------------------------------------
// Prep 1: x fp32 NCHW -> int8 NHWC (tiled transpose through smem, trunc cast)
// grid (2, 56, 128): (wblk, h, n*4+cblk), block (32,32)
// ---------------------------------------------------------------------------
__global__ void prep_x(const float* __restrict__ x) {
    __shared__ signed char t[32][33];
    int wblk = blockIdx.x, h = blockIdx.y;
    int n = blockIdx.z >> 2, cblk = blockIdx.z & 3;

    int w = wblk * 32 + threadIdx.x;
    int c = cblk * 32 + threadIdx.y;
    if (w < HWD) {
        float v = x[(((size_t)n * CIN + c) * HWD + h) * HWD + w];
        t[threadIdx.y][threadIdx.x] = (signed char)(int)v;  // trunc toward zero == jnp.trunc
    }
    __syncthreads();
    int w2 = wblk * 32 + threadIdx.y;
    int c2 = cblk * 32 + threadIdx.x;
    if (w2 < HWD)
        g_x8[(((size_t)n * HWD + h) * HWD + w2) * CIN + c2] = t[threadIdx.x][threadIdx.y];
}

// ---------------------------------------------------------------------------
// Prep 2: weight fp32 OIHW -> int8 [oc][rs*128+c]
// ---------------------------------------------------------------------------
__global__ void prep_w(const float* __restrict__ wt) {
    int i = blockIdx.x * 256 + threadIdx.x;
    if (i < OC * KTOT) {
        int oc = i / KTOT, k = i - oc * KTOT;
        int rs = k >> 7, c = k & 127;
        int r = rs / 3, s = rs - r * 3;
        float v = wt[(((size_t)oc * CIN + c) * 3 + r) * 3 + s];
        g_w8[i] = (signed char)(int)v;
    }
}

// ---------------------------------------------------------------------------
// Main kernel: implicit GEMM, CTA tile 128 pixels x 128 oc, K pipelined 64/stage
// 8 warps: warp tile 64(M) x 32(N). mma.sync m16n8k32 s8s8s32.
// ---------------------------------------------------------------------------
__device__ __forceinline__ void cp16(uint32_t dsm, const void* src, bool ok) {
    int sz = ok ? 16 : 0;
    asm volatile("cp.async.cg.shared.global [%0], [%1], 16, %2;\n"
                 :: "r"(dsm), "l"(src), "r"(sz));
}

__global__ __launch_bounds__(256, 1) void qconv(
    const float* __restrict__ bias, const int* __restrict__ Aq,
    const int* __restrict__ Nq, const int* __restrict__ pmin,
    const int* __restrict__ pmax, float* __restrict__ out)
{
    __shared__ __align__(16) signed char sm[2][2][128 * SSTR];  // [stage][A/B]

    const int tid  = threadIdx.x;
    const int lane = tid & 31, wid = tid >> 5;
    const int gid  = lane >> 2, tg = lane & 3;
    const int warp_m = wid >> 2, warp_n = wid & 3;
    const int p0  = blockIdx.x * 128;
    const int oc0 = blockIdx.y * 128;

    // static per-thread load mapping: 512 16B chunks per operand per stage, 2 per thread
    const int rowb = tid >> 2, part = tid & 3;
    int nn[2], hh[2], ww[2];
    const signed char* wsrc[2];
    uint32_t smoff[2];
#pragma unroll
    for (int i = 0; i < 2; i++) {
        int row = rowb + 64 * i;
        int p = p0 + row;
        nn[i] = p / 3136; int rem = p - nn[i] * 3136;
        hh[i] = rem / 56; ww[i] = rem - hh[i] * 56;
        wsrc[i] = g_w8 + (size_t)(oc0 + row) * KTOT + part * 16;
        smoff[i] = (uint32_t)(row * SSTR + part * 16);
    }
    const uint32_t smbase  = (uint32_t)__cvta_generic_to_shared(&sm[0][0][0]);
    const uint32_t stageSz = 2u * 128 * SSTR;
    const uint32_t Bofs    = 128u * SSTR;

    int acc[4][4][4];
#pragma unroll
    for (int a = 0; a < 4; a++)
#pragma unroll
        for (int b = 0; b < 4; b++)
#pragma unroll
            for (int c = 0; c < 4; c++) acc[a][b][c] = 0;

    auto load_stage = [&](int buf, int ks) {
        int rs = ks >> 1, c0 = (ks & 1) << 6;
        int r = rs / 3, s = rs - r * 3;
#pragma unroll
        for (int i = 0; i < 2; i++) {
            int y = hh[i] + r - 1, xx = ww[i] + s - 1;
            bool ok = ((unsigned)y < HWD) && ((unsigned)xx < HWD);
            int ys = ok ? y : 0, xs = ok ? xx : 0;
            const signed char* asrc =
                g_x8 + (((size_t)nn[i] * HWD + ys) * HWD + xs) * CIN + c0 + part * 16;
            cp16(smbase + buf * stageSz + smoff[i], asrc, ok);
            cp16(smbase + buf * stageSz + Bofs + smoff[i], wsrc[i] + ks * 64, true);
        }
    };

    load_stage(0, 0);
    asm volatile("cp.async.commit_group;\n");

    for (int ks = 0; ks < NSTAGES; ks++) {
        if (ks + 1 < NSTAGES) load_stage((ks + 1) & 1, ks + 1);
        asm volatile("cp.async.commit_group;\n");
        asm volatile("cp.async.wait_group 1;\n");
        __syncthreads();

        const signed char* sA = &sm[ks & 1][0][0];
        const signed char* sB = &sm[ks & 1][1][0];
#pragma unroll
        for (int kk = 0; kk < 64; kk += 32) {
            uint32_t bf[4][2];
#pragma unroll
            for (int nt = 0; nt < 4; nt++) {
                const signed char* bp = sB + (warp_n * 32 + nt * 8 + gid) * SSTR + kk + tg * 4;
                bf[nt][0] = *(const uint32_t*)bp;
                bf[nt][1] = *(const uint32_t*)(bp + 16);
            }
#pragma unroll
            for (int mt = 0; mt < 4; mt++) {
                const signed char* ap = sA + (warp_m * 64 + mt * 16 + gid) * SSTR + kk + tg * 4;
                uint32_t a0 = *(const uint32_t*)ap;
                uint32_t a1 = *(const uint32_t*)(ap + 8 * SSTR);
                uint32_t a2 = *(const uint32_t*)(ap + 16);
                uint32_t a3 = *(const uint32_t*)(ap + 8 * SSTR + 16);
#pragma unroll
                for (int nt = 0; nt < 4; nt++) {
                    asm volatile(
                        "mma.sync.aligned.m16n8k32.row.col.s32.s8.s8.s32 "
                        "{%0,%1,%2,%3}, {%4,%5,%6,%7}, {%8,%9}, {%0,%1,%2,%3};\n"
                        : "+r"(acc[mt][nt][0]), "+r"(acc[mt][nt][1]),
                          "+r"(acc[mt][nt][2]), "+r"(acc[mt][nt][3])
                        : "r"(a0), "r"(a1), "r"(a2), "r"(a3),
                          "r"(bf[nt][0]), "r"(bf[nt][1]));
                }
            }
        }
        __syncthreads();
    }

    // ---- epilogue: bias + requant + round + clip, direct coalesced-by-sector STG ----
    const int omin = *pmin, omax = *pmax;
    float bj[4][2], sc[4][2];
#pragma unroll
    for (int nt = 0; nt < 4; nt++)
#pragma unroll
        for (int j = 0; j < 2; j++) {
            int oc = oc0 + warp_n * 32 + nt * 8 + tg * 2 + j;
            bj[nt][j] = __ldg(&bias[oc]);
            // A * 2^-N : exact float (A < 2^15, power-of-two scale) => single rounding,
            // identical to reference's (f*A)/2^N
            sc[nt][j] = ldexpf((float)__ldg(&Aq[oc]), -__ldg(&Nq[oc]));
        }

#pragma unroll
    for (int mt = 0; mt < 4; mt++) {
#pragma unroll
        for (int hfl = 0; hfl < 2; hfl++) {
            int pix = p0 + warp_m * 64 + mt * 16 + gid + 8 * hfl;
            int n = pix / 3136; int rem = pix - n * 3136;
            float* ob = out + (size_t)n * OC * 3136 + rem;
#pragma unroll
            for (int nt = 0; nt < 4; nt++) {
#pragma unroll
                for (int j = 0; j < 2; j++) {
                    int oc = oc0 + warp_n * 32 + nt * 8 + tg * 2 + j;
                    float f = ((float)acc[mt][nt][hfl * 2 + j] + bj[nt][j]) * sc[nt][j];
                    if (omin >= 0) {
                        f = rintf(f);                       // half-to-even == jnp.round
                        f = fminf(fmaxf(f, (float)omin), (float)omax);
                    }
                    ob[(size_t)oc * 3136] = f;
                }
            }
        }
    }
}

// ---------------------------------------------------------------------------
// Launch. Inputs: x, weight_int, bias_int, A, N, out_min, out_max
// ---------------------------------------------------------------------------
extern "C" void kernel_launch(void* const* d_in, const int* in_sizes, int n_in,
                              void* d_out, int out_size) {
    const float* x    = (const float*)d_in[0];
    const float* w    = (const float*)d_in[1];
    const float* bias = (const float*)d_in[2];
    const int*   Aq   = (const int*)d_in[3];
    const int*   Nq   = (const int*)d_in[4];
    const int*   omin = (const int*)d_in[5];
    const int*   omax = (const int*)d_in[6];
    float* out = (float*)d_out;

    dim3 bt(32, 32), gt(2, HWD, NB * 4);
    prep_x<<<gt, bt>>>(x);
    prep_w<<<(OC * KTOT + 255) / 256, 256>>>(w);

    dim3 grid(/*pixel tiles*/ (NB * HWD * HWD) / 128, /*oc tiles*/ OC / 128);
    qconv<<<grid, 256>>>(bias, Aq, Nq, omin, omax, out);
}

// round 5
// speedup vs baseline: 1.1985x; 1.1985x over previous
#include <cuda_runtime.h>
#include <cstdint>
#include <cstddef>

#define NB   32
#define HWD  56
#define CIN  128
#define OC   256
#define NPIX (NB*HWD*HWD)   // 100352
#define KW   1152           // 9*128

// scratch (no runtime allocation allowed)
__device__ __align__(16) signed char g_x8[(size_t)NPIX * CIN]; // NHWC int8
__device__ __align__(16) signed char g_w8[(size_t)OC * KW];    // [oc][(r*3+s)*128+c]

__device__ __forceinline__ uint32_t smem_u32(const void* p) {
    uint32_t a;
    asm("{ .reg .u64 t; cvta.to.shared.u64 t, %1; cvt.u32.u64 %0, t; }"
        : "=r"(a) : "l"(p));
    return a;
}
#define CPA16(dst, src, sz) \
    asm volatile("cp.async.cg.shared.global [%0], [%1], 16, %2;" \
                 :: "r"(dst), "l"(src), "r"(sz))
#define CPA_COMMIT() asm volatile("cp.async.commit_group;")

__device__ __forceinline__ void ldsm4(uint32_t& r0, uint32_t& r1, uint32_t& r2,
                                      uint32_t& r3, uint32_t addr) {
    asm volatile("ldmatrix.sync.aligned.m8n8.x4.shared.b16 {%0,%1,%2,%3}, [%4];"
                 : "=r"(r0), "=r"(r1), "=r"(r2), "=r"(r3) : "r"(addr));
}

// ---------------------------------------------------------------------------
// Prep 1: x fp32 NCHW -> int8 NHWC. One 256-thread block per (n,h) plane.
// ---------------------------------------------------------------------------
__global__ void prep_x(const float* __restrict__ x) {
    __shared__ signed char t[56 * 132];
    int tid = threadIdx.x;
    int n = blockIdx.x / 56, h = blockIdx.x - n * 56;
    const float* src = x + (size_t)n * CIN * 3136 + h * 56;

    int c = tid / 56, w = tid - c * 56;
#pragma unroll
    for (int i = 0; i < 28; i++) {
        float v = src[(size_t)c * 3136 + w];
        t[w * 132 + c] = (signed char)(int)v;   // trunc toward zero == jnp.trunc
        w += 32; c += 4;
        if (w >= 56) { w -= 56; c += 1; }
    }
    __syncthreads();

    uint32_t* go = (uint32_t*)(g_x8 + (size_t)blockIdx.x * 56 * 128);
#pragma unroll
    for (int i = 0; i < 7; i++) {
        int widx = i * 256 + tid;             // = w*32 + c4
        int ww = widx >> 5, c4 = widx & 31;
        go[widx] = *(const uint32_t*)&t[ww * 132 + c4 * 4];
    }
}

// ---------------------------------------------------------------------------
// Prep 2: weight fp32 OIHW -> int8 [oc][rs*128+c]
// ---------------------------------------------------------------------------
__global__ void prep_w(const float* __restrict__ wt) {
    int i = blockIdx.x * 256 + threadIdx.x;
    if (i < OC * KW) {
        int oc = i / KW, k = i - oc * KW;
        int rs = k >> 7, c = k & 127;
        int r = rs / 3, s = rs - r * 3;
        float v = wt[(((size_t)oc * CIN + c) * 3 + r) * 3 + s];
        g_w8[i] = (signed char)(int)v;
    }
}

// ---------------------------------------------------------------------------
// Main kernel: implicit GEMM via mma.sync m16n8k32 s8s8s32.
// CTA tile 128 pix x 128 oc, K = 1152 as 9 taps of 128, 3-buffer cp.async
// pipeline, ldmatrix.x4 operand feed, XOR-swizzled smem (no padding).
// 8 warps = 2(M) x 4(N); warp tile 64 x 32.
// ---------------------------------------------------------------------------
#define ASZ   16384                 // 128 rows x 128 B
#define STG_SZ 32768                // A + B
#define SMEM_TOTAL (3 * STG_SZ)     // 98304

__global__ void __launch_bounds__(256, 2) qconv(
    const float* __restrict__ bias, const int* __restrict__ Aq,
    const int* __restrict__ Nq, const int* __restrict__ pmin,
    const int* __restrict__ pmax, float* __restrict__ out)
{
    extern __shared__ __align__(128) signed char smem[];
    const uint32_t sb = smem_u32(smem);

    const int tid  = threadIdx.x;
    const int lane = tid & 31, wid = tid >> 5;
    const int gid  = lane >> 2, tg = lane & 3;
    const int warp_m = wid >> 2, warp_n = wid & 3;       // 2 x 4
    const int p0  = blockIdx.x * 128;
    const int oc0 = blockIdx.y * 128;

    // ---- loader mapping: thread -> (row 0..127, half 0..1), 4 chunks each op
    const int row  = tid >> 1, half = tid & 1;
    const int p = p0 + row;
    const int n = p / 3136, rem = p - n * 3136;
    const int h = rem / 56, w = rem - h * 56;
    const signed char* abase = g_x8 + (size_t)p * CIN + half * 64;
    const signed char* bbase = g_w8 + (size_t)(oc0 + row) * KW + half * 64;
    uint32_t sA_off[4], rowbase = (uint32_t)row * 128;
#pragma unroll
    for (int j = 0; j < 4; j++)
        sA_off[j] = rowbase + ((uint32_t)((half * 4 + j) ^ (row & 7)) << 4);

    auto load_stage = [&](int buf, int s) {
        const int rr = s / 3, ss = s - rr * 3;
        const int y = h + rr - 1, xx = w + ss - 1;
        const bool ok = ((unsigned)y < 56u) && ((unsigned)xx < 56u);
        const int sz = ok ? 16 : 0;
        const signed char* asrc = ok ? abase + ((rr - 1) * 56 + (ss - 1)) * CIN : abase;
        const signed char* bsrc = bbase + s * 128;
        const uint32_t da = sb + buf * STG_SZ;
        const uint32_t db = da + ASZ;
#pragma unroll
        for (int j = 0; j < 4; j++) {
            CPA16(da + sA_off[j], asrc + j * 16, sz);
            CPA16(db + sA_off[j], bsrc + j * 16, 16);
        }
    };

    int acc[4][4][4];
#pragma unroll
    for (int a = 0; a < 4; a++)
#pragma unroll
        for (int b = 0; b < 4; b++)
#pragma unroll
            for (int c = 0; c < 4; c++) acc[a][b][c] = 0;

    // ldmatrix per-lane address components (row-in-tile, chunk-half)
    const int lrow = lane & 15;          // row within 16-row tile
    const int lhi  = lane >> 4;          // +1 chunk for matrices 2,3

    load_stage(0, 0); CPA_COMMIT();
    load_stage(1, 1); CPA_COMMIT();

    for (int s = 0; s < 9; s++) {
        const int buf = s % 3;
        asm volatile("cp.async.wait_group 1;");
        __syncthreads();

        if (s + 2 < 9) load_stage((s + 2) % 3, s + 2);
        CPA_COMMIT();

        const uint32_t As = sb + buf * STG_SZ;
        const uint32_t Bs = As + ASZ;
#pragma unroll
        for (int k4 = 0; k4 < 4; k4++) {       // k = k4*32
            uint32_t bf[4][2];
#pragma unroll
            for (int bt = 0; bt < 2; bt++) {   // covers nt = 2*bt, 2*bt+1
                int r = warp_n * 32 + bt * 16 + lrow;
                uint32_t addr = Bs + (uint32_t)r * 128 +
                                ((uint32_t)((k4 * 2 + lhi) ^ (r & 7)) << 4);
                ldsm4(bf[bt * 2][0], bf[bt * 2 + 1][0],
                      bf[bt * 2][1], bf[bt * 2 + 1][1], addr);
            }
#pragma unroll
            for (int mt = 0; mt < 4; mt++) {
                int r = warp_m * 64 + mt * 16 + lrow;
                uint32_t addr = As + (uint32_t)r * 128 +
                                ((uint32_t)((k4 * 2 + lhi) ^ (r & 7)) << 4);
                uint32_t a0, a1, a2, a3;
                ldsm4(a0, a1, a2, a3, addr);
#pragma unroll
                for (int nt = 0; nt < 4; nt++) {
                    asm volatile(
                        "mma.sync.aligned.m16n8k32.row.col.s32.s8.s8.s32 "
                        "{%0,%1,%2,%3}, {%4,%5,%6,%7}, {%8,%9}, {%0,%1,%2,%3};\n"
                        : "+r"(acc[mt][nt][0]), "+r"(acc[mt][nt][1]),
                          "+r"(acc[mt][nt][2]), "+r"(acc[mt][nt][3])
                        : "r"(a0), "r"(a1), "r"(a2), "r"(a3),
                          "r"(bf[nt][0]), "r"(bf[nt][1]));
                }
            }
        }
        __syncthreads();
    }

    // ---- epilogue: bias + requant + round + clip, sector-coalesced STG ----
    const int omin = *pmin, omax = *pmax;
    const float fmin = (float)omin, fmax = (float)omax;
    float bj[4][2], sc[4][2];
#pragma unroll
    for (int nt = 0; nt < 4; nt++)
#pragma unroll
        for (int j = 0; j < 2; j++) {
            int oc = oc0 + warp_n * 32 + nt * 8 + tg * 2 + j;
            bj[nt][j] = __ldg(&bias[oc]);
            // A * 2^-N exact in fp32 => single rounding, identical to (f*A)/2^N
            sc[nt][j] = ldexpf((float)__ldg(&Aq[oc]), -__ldg(&Nq[oc]));
        }

#pragma unroll
    for (int mt = 0; mt < 4; mt++) {
#pragma unroll
        for (int hfl = 0; hfl < 2; hfl++) {
            int pix = p0 + warp_m * 64 + mt * 16 + gid + 8 * hfl;
            int n2 = pix / 3136; int rem2 = pix - n2 * 3136;
            float* ob = out + (size_t)n2 * OC * 3136 + rem2;
#pragma unroll
            for (int nt = 0; nt < 4; nt++) {
#pragma unroll
                for (int j = 0; j < 2; j++) {
                    int oc = oc0 + warp_n * 32 + nt * 8 + tg * 2 + j;
                    float f = ((float)acc[mt][nt][hfl * 2 + j] + bj[nt][j]) * sc[nt][j];
                    if (omin >= 0) {
                        f = rintf(f);                    // half-to-even == jnp.round
                        f = fminf(fmaxf(f, fmin), fmax);
                    }
                    ob[(size_t)oc * 3136] = f;
                }
            }
        }
    }
}

// ---------------------------------------------------------------------------
// Launch. Inputs: x, weight_int, bias_int, A, N, out_min, out_max
// ---------------------------------------------------------------------------
extern "C" void kernel_launch(void* const* d_in, const int* in_sizes, int n_in,
                              void* d_out, int out_size) {
    const float* x    = (const float*)d_in[0];
    const float* wt   = (const float*)d_in[1];
    const float* bias = (const float*)d_in[2];
    const int*   Aq   = (const int*)d_in[3];
    const int*   Nq   = (const int*)d_in[4];
    const int*   omin = (const int*)d_in[5];
    const int*   omax = (const int*)d_in[6];
    float* out = (float*)d_out;

    static int configured = 0;
    if (!configured) {
        cudaFuncSetAttribute(qconv, cudaFuncAttributeMaxDynamicSharedMemorySize,
                             SMEM_TOTAL);
        configured = 1;
    }

    prep_x<<<NB * HWD, 256>>>(x);
    prep_w<<<(OC * KW + 255) / 256, 256>>>(wt);
    dim3 grid(NPIX / 128, OC / 128);
    qconv<<<grid, 256, SMEM_TOTAL>>>(bias, Aq, Nq, omin, omax, out);
}

// round 6
// speedup vs baseline: 1.2956x; 1.0810x over previous
#include <cuda_runtime.h>
#include <cstdint>
#include <cstddef>

#define NB   32
#define HWD  56
#define CIN  128
#define OC   256
#define NPIX (NB*HWD*HWD)   // 100352
#define KW   1152           // 9*128

// scratch (no runtime allocation allowed)
__device__ __align__(16) signed char g_x8[(size_t)NPIX * CIN]; // NHWC int8
__device__ __align__(16) signed char g_w8[(size_t)OC * KW];    // [oc][(r*3+s)*128+c]

__device__ __forceinline__ uint32_t smem_u32(const void* p) {
    uint32_t a;
    asm("{ .reg .u64 t; cvta.to.shared.u64 t, %1; cvt.u32.u64 %0, t; }"
        : "=r"(a) : "l"(p));
    return a;
}
#define CPA16(dst, src, sz) \
    asm volatile("cp.async.cg.shared.global [%0], [%1], 16, %2;" \
                 :: "r"(dst), "l"(src), "r"(sz))
#define CPA_COMMIT() asm volatile("cp.async.commit_group;")

__device__ __forceinline__ void ldsm4(uint32_t& r0, uint32_t& r1, uint32_t& r2,
                                      uint32_t& r3, uint32_t addr) {
    asm volatile("ldmatrix.sync.aligned.m8n8.x4.shared.b16 {%0,%1,%2,%3}, [%4];"
                 : "=r"(r0), "=r"(r1), "=r"(r2), "=r"(r3) : "r"(addr));
}
__device__ __forceinline__ void lds128(int& a, int& b, int& c, int& d, uint32_t addr) {
    asm volatile("ld.shared.v4.u32 {%0,%1,%2,%3}, [%4];"
                 : "=r"(a), "=r"(b), "=r"(c), "=r"(d) : "r"(addr));
}

// ---------------------------------------------------------------------------
// Prep 1: x fp32 NCHW -> int8 NHWC. One 256-thread block per (n,h) plane.
// ---------------------------------------------------------------------------
__global__ void prep_x(const float* __restrict__ x) {
    __shared__ signed char t[56 * 132];
    int tid = threadIdx.x;
    int n = blockIdx.x / 56, h = blockIdx.x - n * 56;
    const float* src = x + (size_t)n * CIN * 3136 + h * 56;

    int c = tid / 56, w = tid - c * 56;
#pragma unroll
    for (int i = 0; i < 28; i++) {
        float v = src[(size_t)c * 3136 + w];
        t[w * 132 + c] = (signed char)(int)v;   // trunc toward zero == jnp.trunc
        w += 32; c += 4;
        if (w >= 56) { w -= 56; c += 1; }
    }
    __syncthreads();

    uint32_t* go = (uint32_t*)(g_x8 + (size_t)blockIdx.x * 56 * 128);
#pragma unroll
    for (int i = 0; i < 7; i++) {
        int widx = i * 256 + tid;             // = w*32 + c4
        int ww = widx >> 5, c4 = widx & 31;
        go[widx] = *(const uint32_t*)&t[ww * 132 + c4 * 4];
    }
}

// ---------------------------------------------------------------------------
// Prep 2: weight fp32 OIHW -> int8 [oc][rs*128+c]
// ---------------------------------------------------------------------------
__global__ void prep_w(const float* __restrict__ wt) {
    int i = blockIdx.x * 256 + threadIdx.x;
    if (i < OC * KW) {
        int oc = i / KW, k = i - oc * KW;
        int rs = k >> 7, c = k & 127;
        int r = rs / 3, s = rs - r * 3;
        float v = wt[(((size_t)oc * CIN + c) * 3 + r) * 3 + s];
        g_w8[i] = (signed char)(int)v;
    }
}

// ---------------------------------------------------------------------------
// Main kernel: dual-engine implicit GEMM.
//   CTA tile 256 pix x 128 oc, K = 9 taps x 128.
//   Warps 0-7 : rows   0-127 via mma.sync m16n8k32 s8 (tensor pipe)
//   Warps 8-15: rows 128-255 via dp4a             (fma pipe)
//   3-buffer cp.async pipeline, XOR-swizzled smem.
// ---------------------------------------------------------------------------
#define ASZ    32768                // 256 rows x 128 B
#define BSZ    16384                // 128 rows x 128 B
#define STG_SZ (ASZ + BSZ)          // 49152
#define SMEM_TOTAL (3 * STG_SZ)     // 147456

__global__ void __launch_bounds__(512, 1) qconv(
    const float* __restrict__ bias, const int* __restrict__ Aq,
    const int* __restrict__ Nq, const int* __restrict__ pmin,
    const int* __restrict__ pmax, float* __restrict__ out)
{
    extern __shared__ __align__(128) signed char smem[];
    const uint32_t sb = smem_u32(smem);

    const int tid  = threadIdx.x;
    const int lane = tid & 31, wid = tid >> 5;
    const int p0  = blockIdx.x * 256;
    const int oc0 = blockIdx.y * 128;

    // ---- loader mapping ----
    // A: 256 rows x 8 chunks(16B) = 2048 chunks; thread -> (row=t>>1, half=t&1), 4 chunks
    // B: 128 rows x 8 chunks = 1024 chunks; thread -> (row=t>>2, quarter), 2 chunks
    const int rowA  = tid >> 1, halfA = tid & 1;
    const int pA = p0 + rowA;
    const int nA = pA / 3136, remA = pA - nA * 3136;
    const int hA = remA / 56, wA = remA - hA * 56;
    const signed char* abase = g_x8 + (size_t)pA * CIN + halfA * 64;
    uint32_t offA[4];
#pragma unroll
    for (int j = 0; j < 4; j++)
        offA[j] = (uint32_t)rowA * 128 +
                  ((uint32_t)((halfA * 4 + j) ^ (rowA & 7)) << 4);

    const int rowB = tid >> 2, qB = tid & 3;
    const signed char* bbase = g_w8 + (size_t)(oc0 + rowB) * KW + qB * 32;
    uint32_t offB[2];
#pragma unroll
    for (int j = 0; j < 2; j++)
        offB[j] = (uint32_t)rowB * 128 +
                  ((uint32_t)((qB * 2 + j) ^ (rowB & 7)) << 4);

    auto load_stage = [&](int buf, int s) {
        const int rr = s / 3, ss = s - rr * 3;
        const int y = hA + rr - 1, xx = wA + ss - 1;
        const bool ok = ((unsigned)y < 56u) && ((unsigned)xx < 56u);
        const int sz = ok ? 16 : 0;
        const signed char* asrc = ok ? abase + ((rr - 1) * 56 + (ss - 1)) * CIN : abase;
        const signed char* bsrc = bbase + s * 128;
        const uint32_t da = sb + buf * STG_SZ;
        const uint32_t db = da + ASZ;
#pragma unroll
        for (int j = 0; j < 4; j++) CPA16(da + offA[j], asrc + j * 16, sz);
#pragma unroll
        for (int j = 0; j < 2; j++) CPA16(db + offB[j], bsrc + j * 16, 16);
    };

    // ---- per-engine state ----
    // IMMA warps (0-7): 2(M) x 4(N) grid, warp tile 64x32 over rows 0-127
    const int warp_m = (wid >> 2) & 1, warp_n = wid & 3;
    const int gid  = lane >> 2, tg = lane & 3;
    const int lrow = lane & 15, lhi = lane >> 4;
    int acc[4][4][4];
#pragma unroll
    for (int a = 0; a < 4; a++)
#pragma unroll
        for (int b = 0; b < 4; b++)
#pragma unroll
            for (int c = 0; c < 4; c++) acc[a][b][c] = 0;

    // dp4a warps (8-15): warp handles rows 128 + (wid-8)*16 .. +15, all 128 oc
    // lane: rowg = lane>>3 (4 rows of rowg*4+r), ocg = lane&7, ocs = ocg + 8j
    const int rowg = lane >> 3, ocg = lane & 7;
    const int dRB = 128 + (wid - 8) * 16 + rowg * 4;   // tile row of r=0
    int dacc[4][16];
#pragma unroll
    for (int r = 0; r < 4; r++)
#pragma unroll
        for (int j = 0; j < 16; j++) dacc[r][j] = 0;

    load_stage(0, 0); CPA_COMMIT();
    load_stage(1, 1); CPA_COMMIT();

    for (int s = 0; s < 9; s++) {
        const int buf = s % 3;
        asm volatile("cp.async.wait_group 1;");
        __syncthreads();

        if (s + 2 < 9) load_stage((s + 2) % 3, s + 2);
        CPA_COMMIT();

        const uint32_t As = sb + buf * STG_SZ;
        const uint32_t Bs = As + ASZ;

        if (wid < 8) {
            // ---------------- tensor-pipe half ----------------
#pragma unroll
            for (int k4 = 0; k4 < 4; k4++) {
                uint32_t bf[4][2];
#pragma unroll
                for (int bt = 0; bt < 2; bt++) {
                    int r = warp_n * 32 + bt * 16 + lrow;
                    uint32_t addr = Bs + (uint32_t)r * 128 +
                                    ((uint32_t)((k4 * 2 + lhi) ^ (r & 7)) << 4);
                    ldsm4(bf[bt * 2][0], bf[bt * 2 + 1][0],
                          bf[bt * 2][1], bf[bt * 2 + 1][1], addr);
                }
#pragma unroll
                for (int mt = 0; mt < 4; mt++) {
                    int r = warp_m * 64 + mt * 16 + lrow;
                    uint32_t addr = As + (uint32_t)r * 128 +
                                    ((uint32_t)((k4 * 2 + lhi) ^ (r & 7)) << 4);
                    uint32_t a0, a1, a2, a3;
                    ldsm4(a0, a1, a2, a3, addr);
#pragma unroll
                    for (int nt = 0; nt < 4; nt++) {
                        asm volatile(
                            "mma.sync.aligned.m16n8k32.row.col.s32.s8.s8.s32 "
                            "{%0,%1,%2,%3}, {%4,%5,%6,%7}, {%8,%9}, {%0,%1,%2,%3};\n"
                            : "+r"(acc[mt][nt][0]), "+r"(acc[mt][nt][1]),
                              "+r"(acc[mt][nt][2]), "+r"(acc[mt][nt][3])
                            : "r"(a0), "r"(a1), "r"(a2), "r"(a3),
                              "r"(bf[nt][0]), "r"(bf[nt][1]));
                    }
                }
            }
        } else {
            // ---------------- fma-pipe (dp4a) half ----------------
#pragma unroll
            for (int k16 = 0; k16 < 8; k16++) {
                int av[4][4];
#pragma unroll
                for (int r = 0; r < 4; r++) {
                    int row = dRB + r;
                    uint32_t addr = As + (uint32_t)row * 128 +
                                    ((uint32_t)(k16 ^ (row & 7)) << 4);
                    lds128(av[r][0], av[r][1], av[r][2], av[r][3], addr);
                }
                const uint32_t bchunk = (uint32_t)(k16 ^ ocg) << 4;
#pragma unroll
                for (int jc = 0; jc < 4; jc++) {
                    int bv[4][4];
#pragma unroll
                    for (int jj = 0; jj < 4; jj++) {
                        int ocrow = ocg + 8 * (jc * 4 + jj);
                        uint32_t addr = Bs + (uint32_t)ocrow * 128 + bchunk;
                        lds128(bv[jj][0], bv[jj][1], bv[jj][2], bv[jj][3], addr);
                    }
#pragma unroll
                    for (int r = 0; r < 4; r++)
#pragma unroll
                        for (int jj = 0; jj < 4; jj++) {
                            int j = jc * 4 + jj;
                            int v = dacc[r][j];
                            v = __dp4a(av[r][0], bv[jj][0], v);
                            v = __dp4a(av[r][1], bv[jj][1], v);
                            v = __dp4a(av[r][2], bv[jj][2], v);
                            v = __dp4a(av[r][3], bv[jj][3], v);
                            dacc[r][j] = v;
                        }
                }
            }
        }
        __syncthreads();
    }

    // ---- epilogue: bias + requant + round + clip ----
    const int omin = *pmin, omax = *pmax;
    const float fmin = (float)omin, fmax = (float)omax;

    if (wid < 8) {
        float bj[4][2], sc[4][2];
#pragma unroll
        for (int nt = 0; nt < 4; nt++)
#pragma unroll
            for (int j = 0; j < 2; j++) {
                int oc = oc0 + warp_n * 32 + nt * 8 + tg * 2 + j;
                bj[nt][j] = __ldg(&bias[oc]);
                sc[nt][j] = ldexpf((float)__ldg(&Aq[oc]), -__ldg(&Nq[oc]));
            }
#pragma unroll
        for (int mt = 0; mt < 4; mt++) {
#pragma unroll
            for (int hfl = 0; hfl < 2; hfl++) {
                int pix = p0 + warp_m * 64 + mt * 16 + gid + 8 * hfl;
                int n2 = pix / 3136; int rem2 = pix - n2 * 3136;
                float* ob = out + (size_t)n2 * OC * 3136 + rem2;
#pragma unroll
                for (int nt = 0; nt < 4; nt++) {
#pragma unroll
                    for (int j = 0; j < 2; j++) {
                        int oc = oc0 + warp_n * 32 + nt * 8 + tg * 2 + j;
                        float f = ((float)acc[mt][nt][hfl * 2 + j] + bj[nt][j]) * sc[nt][j];
                        if (omin >= 0) {
                            f = rintf(f);
                            f = fminf(fmaxf(f, fmin), fmax);
                        }
                        ob[(size_t)oc * 3136] = f;
                    }
                }
            }
        }
    } else {
        float bj[16], sc[16];
#pragma unroll
        for (int j = 0; j < 16; j++) {
            int oc = oc0 + ocg + 8 * j;
            bj[j] = __ldg(&bias[oc]);
            sc[j] = ldexpf((float)__ldg(&Aq[oc]), -__ldg(&Nq[oc]));
        }
#pragma unroll
        for (int r = 0; r < 4; r++) {
            int pix = p0 + dRB + r;
            int n2 = pix / 3136; int rem2 = pix - n2 * 3136;
            float* ob = out + (size_t)n2 * OC * 3136 + rem2;
#pragma unroll
            for (int j = 0; j < 16; j++) {
                int oc = oc0 + ocg + 8 * j;
                float f = ((float)dacc[r][j] + bj[j]) * sc[j];
                if (omin >= 0) {
                    f = rintf(f);
                    f = fminf(fmaxf(f, fmin), fmax);
                }
                ob[(size_t)oc * 3136] = f;
            }
        }
    }
}

// ---------------------------------------------------------------------------
// Launch. Inputs: x, weight_int, bias_int, A, N, out_min, out_max
// ---------------------------------------------------------------------------
extern "C" void kernel_launch(void* const* d_in, const int* in_sizes, int n_in,
                              void* d_out, int out_size) {
    const float* x    = (const float*)d_in[0];
    const float* wt   = (const float*)d_in[1];
    const float* bias = (const float*)d_in[2];
    const int*   Aq   = (const int*)d_in[3];
    const int*   Nq   = (const int*)d_in[4];
    const int*   omin = (const int*)d_in[5];
    const int*   omax = (const int*)d_in[6];
    float* out = (float*)d_out;

    static int configured = 0;
    if (!configured) {
        cudaFuncSetAttribute(qconv, cudaFuncAttributeMaxDynamicSharedMemorySize,
                             SMEM_TOTAL);
        configured = 1;
    }

    prep_x<<<NB * HWD, 256>>>(x);
    prep_w<<<(OC * KW + 255) / 256, 256>>>(wt);
    dim3 grid(NPIX / 256, OC / 128);
    qconv<<<grid, 512, SMEM_TOTAL>>>(bias, Aq, Nq, omin, omax, out);
}

// round 7
// speedup vs baseline: 1.3968x; 1.0782x over previous
#include <cuda_runtime.h>
#include <cuda_fp16.h>
#include <cstdint>
#include <cstddef>

#define NB   32
#define HWD  56
#define CIN  128
#define OC   256
#define NPIX (NB*HWD*HWD)   // 100352
#define KW   1152           // 9*128

// scratch (no runtime allocation allowed)
__device__ __align__(16) __half g_x16[(size_t)NPIX * CIN]; // NHWC fp16 (exact ints)
__device__ __align__(16) __half g_w16[(size_t)OC * KW];    // [oc][(r*3+s)*128+c]

__device__ __forceinline__ uint32_t smem_u32(const void* p) {
    uint32_t a;
    asm("{ .reg .u64 t; cvta.to.shared.u64 t, %1; cvt.u32.u64 %0, t; }"
        : "=r"(a) : "l"(p));
    return a;
}
#define CPA16(dst, src, sz) \
    asm volatile("cp.async.cg.shared.global [%0], [%1], 16, %2;" \
                 :: "r"(dst), "l"(src), "r"(sz))
#define CPA_COMMIT() asm volatile("cp.async.commit_group;")

__device__ __forceinline__ void ldsm4(uint32_t& r0, uint32_t& r1, uint32_t& r2,
                                      uint32_t& r3, uint32_t addr) {
    asm volatile("ldmatrix.sync.aligned.m8n8.x4.shared.b16 {%0,%1,%2,%3}, [%4];"
                 : "=r"(r0), "=r"(r1), "=r"(r2), "=r"(r3) : "r"(addr));
}

// swizzled smem address: 256B rows as two 128B halves, XOR swizzle per half
__device__ __forceinline__ uint32_t sw_addr(uint32_t base, int r, int chunk) {
    return base + (uint32_t)r * 256 + (uint32_t)((chunk >> 3) << 7)
                + ((uint32_t)(((chunk & 7) ^ (r & 7))) << 4);
}

// ---------------------------------------------------------------------------
// Prep 1: x fp32 NCHW -> fp16 NHWC. One 256-thread block per (n,h) plane.
// ---------------------------------------------------------------------------
__global__ void prep_x(const float* __restrict__ x) {
    __shared__ __half t[56 * 132];
    int tid = threadIdx.x;
    int n = blockIdx.x / 56, h = blockIdx.x - n * 56;
    const float* src = x + (size_t)n * CIN * 3136 + h * 56;

    int c = tid / 56, w = tid - c * 56;
#pragma unroll
    for (int i = 0; i < 28; i++) {
        float v = src[(size_t)c * 3136 + w];
        t[w * 132 + c] = __float2half_rn((float)(int)v);  // trunc == jnp.trunc, exact
        w += 32; c += 4;
        if (w >= 56) { w -= 56; c += 1; }
    }
    __syncthreads();

    uint2* go = (uint2*)(g_x16 + (size_t)blockIdx.x * 56 * 128);
#pragma unroll
    for (int i = 0; i < 7; i++) {
        int widx = i * 256 + tid;             // = w*32 + c4 (4 halves per slot)
        int ww = widx >> 5, c4 = widx & 31;
        go[widx] = *(const uint2*)&t[ww * 132 + c4 * 4];
    }
}

// ---------------------------------------------------------------------------
// Prep 2: weight fp32 OIHW -> fp16 [oc][rs*128+c]
// ---------------------------------------------------------------------------
__global__ void prep_w(const float* __restrict__ wt) {
    int i = blockIdx.x * 256 + threadIdx.x;
    if (i < OC * KW) {
        int oc = i / KW, k = i - oc * KW;
        int rs = k >> 7, c = k & 127;
        int r = rs / 3, s = rs - r * 3;
        float v = wt[(((size_t)oc * CIN + c) * 3 + r) * 3 + s];
        g_w16[i] = __float2half_rn((float)(int)v);
    }
}

// ---------------------------------------------------------------------------
// Main kernel: implicit GEMM via mma.sync m16n8k16 f16 (f32 accum).
// CTA tile 128 pix x 128 oc, K = 9 taps x 128 (256B rows), 3-stage cp.async,
// ldmatrix.x4 feed. 8 warps = 2(M) x 4(N); warp tile 64 x 32.
// ---------------------------------------------------------------------------
#define ASZ    32768                // 128 rows x 256 B
#define STG_SZ 65536                // A + B
#define SMEM_TOTAL (3 * STG_SZ)     // 196608

__global__ void __launch_bounds__(256, 1) qconv(
    const float* __restrict__ bias, const int* __restrict__ Aq,
    const int* __restrict__ Nq, const int* __restrict__ pmin,
    const int* __restrict__ pmax, float* __restrict__ out)
{
    extern __shared__ __align__(128) signed char smem[];
    const uint32_t sb = smem_u32(smem);

    const int tid  = threadIdx.x;
    const int lane = tid & 31, wid = tid >> 5;
    const int gid  = lane >> 2, tg = lane & 3;
    const int warp_m = wid >> 2, warp_n = wid & 3;       // 2 x 4
    const int p0  = blockIdx.x * 128;
    const int oc0 = blockIdx.y * 128;

    // loader: thread -> (row = tid>>1, cq = tid&1), 8 x 16B chunks per operand
    const int row = tid >> 1, cq = tid & 1;
    const int p = p0 + row;
    const int n = p / 3136, rem = p - n * 3136;
    const int h = rem / 56, w = rem - h * 56;
    const __half* abase = g_x16 + (size_t)p * CIN + cq * 64;      // 64 halves = 128B
    const __half* bbase = g_w16 + (size_t)(oc0 + row) * KW + cq * 64;
    uint32_t soff[8];
#pragma unroll
    for (int j = 0; j < 8; j++)
        soff[j] = (uint32_t)row * 256 + (uint32_t)(cq << 7)
                + ((uint32_t)((j ^ (row & 7))) << 4);

    auto load_stage = [&](int buf, int s) {
        const int rr = s / 3, ss = s - rr * 3;
        const int y = h + rr - 1, xx = w + ss - 1;
        const bool ok = ((unsigned)y < 56u) && ((unsigned)xx < 56u);
        const int sz = ok ? 16 : 0;
        const __half* asrc = ok ? abase + ((rr - 1) * 56 + (ss - 1)) * CIN : abase;
        const __half* bsrc = bbase + s * 128;
        const uint32_t da = sb + buf * STG_SZ;
        const uint32_t db = da + ASZ;
#pragma unroll
        for (int j = 0; j < 8; j++) {
            CPA16(da + soff[j], asrc + j * 8, sz);
            CPA16(db + soff[j], bsrc + j * 8, 16);
        }
    };

    float acc[4][4][4];
#pragma unroll
    for (int a = 0; a < 4; a++)
#pragma unroll
        for (int b = 0; b < 4; b++)
#pragma unroll
            for (int c = 0; c < 4; c++) acc[a][b][c] = 0.0f;

    const int lrow = lane & 15;          // row within 16-row tile
    const int lhi  = lane >> 4;          // chunk select for matrices 2,3

    load_stage(0, 0); CPA_COMMIT();
    load_stage(1, 1); CPA_COMMIT();

    for (int s = 0; s < 9; s++) {
        const int buf = s % 3;
        asm volatile("cp.async.wait_group 1;");
        __syncthreads();

        if (s + 2 < 9) load_stage((s + 2) % 3, s + 2);
        CPA_COMMIT();

        const uint32_t As = sb + buf * STG_SZ;
        const uint32_t Bs = As + ASZ;
#pragma unroll
        for (int k = 0; k < 8; k++) {          // k16 steps; chunk = 2k + lhi
            uint32_t bf[4][2];
#pragma unroll
            for (int bt = 0; bt < 2; bt++) {
                int r = warp_n * 32 + bt * 16 + lrow;
                ldsm4(bf[bt * 2][0], bf[bt * 2 + 1][0],
                      bf[bt * 2][1], bf[bt * 2 + 1][1],
                      sw_addr(Bs, r, 2 * k + lhi));
            }
#pragma unroll
            for (int mt = 0; mt < 4; mt++) {
                int r = warp_m * 64 + mt * 16 + lrow;
                uint32_t a0, a1, a2, a3;
                ldsm4(a0, a1, a2, a3, sw_addr(As, r, 2 * k + lhi));
#pragma unroll
                for (int nt = 0; nt < 4; nt++) {
                    asm volatile(
                        "mma.sync.aligned.m16n8k16.row.col.f32.f16.f16.f32 "
                        "{%0,%1,%2,%3}, {%4,%5,%6,%7}, {%8,%9}, {%0,%1,%2,%3};\n"
                        : "+f"(acc[mt][nt][0]), "+f"(acc[mt][nt][1]),
                          "+f"(acc[mt][nt][2]), "+f"(acc[mt][nt][3])
                        : "r"(a0), "r"(a1), "r"(a2), "r"(a3),
                          "r"(bf[nt][0]), "r"(bf[nt][1]));
                }
            }
        }
        __syncthreads();
    }

    // ---- epilogue: bias + requant + round + clip, sector-coalesced STG ----
    const int omin = *pmin, omax = *pmax;
    const float fmin = (float)omin, fmax = (float)omax;
    float bj[4][2], sc[4][2];
#pragma unroll
    for (int nt = 0; nt < 4; nt++)
#pragma unroll
        for (int j = 0; j < 2; j++) {
            int oc = oc0 + warp_n * 32 + nt * 8 + tg * 2 + j;
            bj[nt][j] = __ldg(&bias[oc]);
            // A * 2^-N exact in fp32 => single rounding == (f*A)/2^N
            sc[nt][j] = ldexpf((float)__ldg(&Aq[oc]), -__ldg(&Nq[oc]));
        }

#pragma unroll
    for (int mt = 0; mt < 4; mt++) {
#pragma unroll
        for (int hfl = 0; hfl < 2; hfl++) {
            int pix = p0 + warp_m * 64 + mt * 16 + gid + 8 * hfl;
            int n2 = pix / 3136; int rem2 = pix - n2 * 3136;
            float* ob = out + (size_t)n2 * OC * 3136 + rem2;
#pragma unroll
            for (int nt = 0; nt < 4; nt++) {
#pragma unroll
                for (int j = 0; j < 2; j++) {
                    int oc = oc0 + warp_n * 32 + nt * 8 + tg * 2 + j;
                    float f = (acc[mt][nt][hfl * 2 + j] + bj[nt][j]) * sc[nt][j];
                    if (omin >= 0) {
                        f = rintf(f);                    // half-to-even == jnp.round
                        f = fminf(fmaxf(f, fmin), fmax);
                    }
                    ob[(size_t)oc * 3136] = f;
                }
            }
        }
    }
}

// ---------------------------------------------------------------------------
// Launch. Inputs: x, weight_int, bias_int, A, N, out_min, out_max
// ---------------------------------------------------------------------------
extern "C" void kernel_launch(void* const* d_in, const int* in_sizes, int n_in,
                              void* d_out, int out_size) {
    const float* x    = (const float*)d_in[0];
    const float* wt   = (const float*)d_in[1];
    const float* bias = (const float*)d_in[2];
    const int*   Aq   = (const int*)d_in[3];
    const int*   Nq   = (const int*)d_in[4];
    const int*   omin = (const int*)d_in[5];
    const int*   omax = (const int*)d_in[6];
    float* out = (float*)d_out;

    static int configured = 0;
    if (!configured) {
        cudaFuncSetAttribute(qconv, cudaFuncAttributeMaxDynamicSharedMemorySize,
                             SMEM_TOTAL);
        configured = 1;
    }

    prep_x<<<NB * HWD, 256>>>(x);
    prep_w<<<(OC * KW + 255) / 256, 256>>>(wt);
    dim3 grid(NPIX / 128, OC / 128);
    qconv<<<grid, 256, SMEM_TOTAL>>>(bias, Aq, Nq, omin, omax, out);
}

// round 8
// speedup vs baseline: 2.1095x; 1.5102x over previous
#include <cuda_runtime.h>
#include <cuda_fp16.h>
#include <cstdint>
#include <cstddef>

#define NB   32
#define HWD  56
#define CIN  128
#define OC   256
#define NPIX (NB*HWD*HWD)   // 100352
#define KW   1152           // 9*128

// scratch (no runtime allocation allowed)
__device__ __align__(16) __half g_x16[(size_t)NPIX * CIN]; // NHWC fp16 (exact ints)
__device__ __align__(16) __half g_w16[(size_t)OC * KW];    // [oc][(r*3+s)*128+c]

__device__ __forceinline__ uint32_t smem_u32(const void* p) {
    uint32_t a;
    asm("{ .reg .u64 t; cvta.to.shared.u64 t, %1; cvt.u32.u64 %0, t; }"
        : "=r"(a) : "l"(p));
    return a;
}
#define CPA16(dst, src, sz) \
    asm volatile("cp.async.cg.shared.global [%0], [%1], 16, %2;" \
                 :: "r"(dst), "l"(src), "r"(sz))
#define CPA_COMMIT() asm volatile("cp.async.commit_group;")

__device__ __forceinline__ void ldsm4(uint32_t& r0, uint32_t& r1, uint32_t& r2,
                                      uint32_t& r3, uint32_t addr) {
    asm volatile("ldmatrix.sync.aligned.m8n8.x4.shared.b16 {%0,%1,%2,%3}, [%4];"
                 : "=r"(r0), "=r"(r1), "=r"(r2), "=r"(r3) : "r"(addr));
}

// ---------------------------------------------------------------------------
// Prep 1: x fp32 NCHW -> fp16 NHWC. One 256-thread block per (n,h) plane.
// ---------------------------------------------------------------------------
__global__ void prep_x(const float* __restrict__ x) {
    __shared__ __half t[56 * 132];
    int tid = threadIdx.x;
    int n = blockIdx.x / 56, h = blockIdx.x - n * 56;
    const float* src = x + (size_t)n * CIN * 3136 + h * 56;

    int c = tid / 56, w = tid - c * 56;
#pragma unroll
    for (int i = 0; i < 28; i++) {
        float v = src[(size_t)c * 3136 + w];
        t[w * 132 + c] = __float2half_rn((float)(int)v);  // trunc == jnp.trunc, exact
        w += 32; c += 4;
        if (w >= 56) { w -= 56; c += 1; }
    }
    __syncthreads();

    uint2* go = (uint2*)(g_x16 + (size_t)blockIdx.x * 56 * 128);
#pragma unroll
    for (int i = 0; i < 7; i++) {
        int widx = i * 256 + tid;
        int ww = widx >> 5, c4 = widx & 31;
        go[widx] = *(const uint2*)&t[ww * 132 + c4 * 4];
    }
}

// ---------------------------------------------------------------------------
// Prep 2: weight fp32 OIHW -> fp16 [oc][rs*128+c]
// ---------------------------------------------------------------------------
__global__ void prep_w(const float* __restrict__ wt) {
    int i = blockIdx.x * 256 + threadIdx.x;
    if (i < OC * KW) {
        int oc = i / KW, k = i - oc * KW;
        int rs = k >> 7, c = k & 127;
        int r = rs / 3, s = rs - r * 3;
        float v = wt[(((size_t)oc * CIN + c) * 3 + r) * 3 + s];
        g_w16[i] = __float2half_rn((float)(int)v);
    }
}

// ---------------------------------------------------------------------------
// Main kernel: implicit GEMM via mma.sync m16n8k16 f16 (f32 accum).
// CTA tile 128 pix x 128 oc; K = 18 stages of 64 channels (half taps).
// 3-buffer cp.async pipeline, 96KB smem -> 2 CTAs/SM (4 warps/SMSP).
// 8 warps = 2(M) x 4(N); warp tile 64 x 32.
// ---------------------------------------------------------------------------
#define ASZ    16384                // 128 rows x 128 B (64 halves)
#define STG_SZ 32768                // A + B
#define SMEM_TOTAL (3 * STG_SZ)     // 98304

__global__ void __launch_bounds__(256, 2) qconv(
    const float* __restrict__ bias, const int* __restrict__ Aq,
    const int* __restrict__ Nq, const int* __restrict__ pmin,
    const int* __restrict__ pmax, float* __restrict__ out)
{
    extern __shared__ __align__(128) signed char smem[];
    const uint32_t sb = smem_u32(smem);

    const int tid  = threadIdx.x;
    const int lane = tid & 31, wid = tid >> 5;
    const int gid  = lane >> 2, tg = lane & 3;
    const int warp_m = wid >> 2, warp_n = wid & 3;       // 2 x 4
    const int p0  = blockIdx.x * 128;
    const int oc0 = blockIdx.y * 128;

    // loader: thread -> (row = tid>>1, halfA = tid&1), 4 x 16B chunks / operand
    const int row = tid >> 1, halfA = tid & 1;
    const int p = p0 + row;
    const int n = p / 3136, rem = p - n * 3136;
    const int h = rem / 56, w = rem - h * 56;
    const __half* abase = g_x16 + (size_t)p * CIN + halfA * 32;       // +64B
    const __half* bbase = g_w16 + (size_t)(oc0 + row) * KW + halfA * 32;
    uint32_t soff[4];
#pragma unroll
    for (int j = 0; j < 4; j++)
        soff[j] = (uint32_t)row * 128 +
                  ((uint32_t)((halfA * 4 + j) ^ (row & 7)) << 4);

    // stage s (0..17): tap = s>>1, channel half = s&1
    auto load_stage = [&](int buf, int s) {
        const int tap = s >> 1, ch = s & 1;
        const int rr = tap / 3, ss = tap - rr * 3;
        const int y = h + rr - 1, xx = w + ss - 1;
        const bool ok = ((unsigned)y < 56u) && ((unsigned)xx < 56u);
        const int sz = ok ? 16 : 0;
        const __half* asrc = (ok ? abase + ((rr - 1) * 56 + (ss - 1)) * CIN : abase)
                             + ch * 64;
        const __half* bsrc = bbase + s * 64;
        const uint32_t da = sb + buf * STG_SZ;
        const uint32_t db = da + ASZ;
#pragma unroll
        for (int j = 0; j < 4; j++) {
            CPA16(da + soff[j], asrc + j * 8, sz);
            CPA16(db + soff[j], bsrc + j * 8, 16);
        }
    };

    float acc[4][4][4];
#pragma unroll
    for (int a = 0; a < 4; a++)
#pragma unroll
        for (int b = 0; b < 4; b++)
#pragma unroll
            for (int c = 0; c < 4; c++) acc[a][b][c] = 0.0f;

    const int lrow = lane & 15;          // row within 16-row tile
    const int lhi  = lane >> 4;          // chunk select for matrices 2,3

    load_stage(0, 0); CPA_COMMIT();
    load_stage(1, 1); CPA_COMMIT();

    for (int s = 0; s < 18; s++) {
        const int buf = s % 3;
        asm volatile("cp.async.wait_group 1;");
        __syncthreads();

        if (s + 2 < 18) load_stage((s + 2) % 3, s + 2);
        CPA_COMMIT();

        const uint32_t As = sb + buf * STG_SZ;
        const uint32_t Bs = As + ASZ;
#pragma unroll
        for (int k = 0; k < 4; k++) {          // k16 steps; 16B chunk = 2k+lhi
            uint32_t bf[4][2];
#pragma unroll
            for (int bt = 0; bt < 2; bt++) {
                int r = warp_n * 32 + bt * 16 + lrow;
                uint32_t addr = Bs + (uint32_t)r * 128 +
                                ((uint32_t)((2 * k + lhi) ^ (r & 7)) << 4);
                ldsm4(bf[bt * 2][0], bf[bt * 2 + 1][0],
                      bf[bt * 2][1], bf[bt * 2 + 1][1], addr);
            }
#pragma unroll
            for (int mt = 0; mt < 4; mt++) {
                int r = warp_m * 64 + mt * 16 + lrow;
                uint32_t addr = As + (uint32_t)r * 128 +
                                ((uint32_t)((2 * k + lhi) ^ (r & 7)) << 4);
                uint32_t a0, a1, a2, a3;
                ldsm4(a0, a1, a2, a3, addr);
#pragma unroll
                for (int nt = 0; nt < 4; nt++) {
                    asm volatile(
                        "mma.sync.aligned.m16n8k16.row.col.f32.f16.f16.f32 "
                        "{%0,%1,%2,%3}, {%4,%5,%6,%7}, {%8,%9}, {%0,%1,%2,%3};\n"
                        : "+f"(acc[mt][nt][0]), "+f"(acc[mt][nt][1]),
                          "+f"(acc[mt][nt][2]), "+f"(acc[mt][nt][3])
                        : "r"(a0), "r"(a1), "r"(a2), "r"(a3),
                          "r"(bf[nt][0]), "r"(bf[nt][1]));
                }
            }
        }
        __syncthreads();
    }

    // ---- epilogue: bias + requant + round + clip, sector-coalesced STG ----
    const int omin = *pmin, omax = *pmax;
    const float fmin = (float)omin, fmax = (float)omax;
    float bj[4][2], sc[4][2];
#pragma unroll
    for (int nt = 0; nt < 4; nt++)
#pragma unroll
        for (int j = 0; j < 2; j++) {
            int oc = oc0 + warp_n * 32 + nt * 8 + tg * 2 + j;
            bj[nt][j] = __ldg(&bias[oc]);
            // A * 2^-N exact in fp32 => single rounding == (f*A)/2^N
            sc[nt][j] = ldexpf((float)__ldg(&Aq[oc]), -__ldg(&Nq[oc]));
        }

#pragma unroll
    for (int mt = 0; mt < 4; mt++) {
#pragma unroll
        for (int hfl = 0; hfl < 2; hfl++) {
            int pix = p0 + warp_m * 64 + mt * 16 + gid + 8 * hfl;
            int n2 = pix / 3136; int rem2 = pix - n2 * 3136;
            float* ob = out + (size_t)n2 * OC * 3136 + rem2;
#pragma unroll
            for (int nt = 0; nt < 4; nt++) {
#pragma unroll
                for (int j = 0; j < 2; j++) {
                    int oc = oc0 + warp_n * 32 + nt * 8 + tg * 2 + j;
                    float f = (acc[mt][nt][hfl * 2 + j] + bj[nt][j]) * sc[nt][j];
                    if (omin >= 0) {
                        f = rintf(f);                    // half-to-even == jnp.round
                        f = fminf(fmaxf(f, fmin), fmax);
                    }
                    ob[(size_t)oc * 3136] = f;
                }
            }
        }
    }
}

// ---------------------------------------------------------------------------
// Launch. Inputs: x, weight_int, bias_int, A, N, out_min, out_max
// ---------------------------------------------------------------------------
extern "C" void kernel_launch(void* const* d_in, const int* in_sizes, int n_in,
                              void* d_out, int out_size) {
    const float* x    = (const float*)d_in[0];
    const float* wt   = (const float*)d_in[1];
    const float* bias = (const float*)d_in[2];
    const int*   Aq   = (const int*)d_in[3];
    const int*   Nq   = (const int*)d_in[4];
    const int*   omin = (const int*)d_in[5];
    const int*   omax = (const int*)d_in[6];
    float* out = (float*)d_out;

    static int configured = 0;
    if (!configured) {
        cudaFuncSetAttribute(qconv, cudaFuncAttributeMaxDynamicSharedMemorySize,
                             SMEM_TOTAL);
        configured = 1;
    }

    prep_x<<<NB * HWD, 256>>>(x);
    prep_w<<<(OC * KW + 255) / 256, 256>>>(wt);
    dim3 grid(NPIX / 128, OC / 128);
    qconv<<<grid, 256, SMEM_TOTAL>>>(bias, Aq, Nq, omin, omax, out);
}